// round 2
// baseline (speedup 1.0000x reference)
#include <cuda_runtime.h>
#include <cuda_bf16.h>
#include <cstdint>

#define BB 256
#define TENC 512
#define TDEC 64
#define DD 64
#define HH 512
#define OO 512
#define G4 2048            // 4*H
#define KHX 576            // H + D
#define NCH 18             // KHX / 32
#define OUT_OFS ((size_t)BB * TDEC * OO)   // 8388608 floats: dec_outputs, then dec_hiddens

// ---------------- device-global scratch (no cudaMalloc allowed) ----------------
__device__ __nv_bfloat16 g_W_hi[2][G4 * KHX];
__device__ __nv_bfloat16 g_W_lo[2][G4 * KHX];
__device__ float         g_bias[2][G4];
__device__ __nv_bfloat16 g_x_hi[(TENC + TDEC) * BB * DD];
__device__ __nv_bfloat16 g_x_lo[(TENC + TDEC) * BB * DD];
__device__ __nv_bfloat16 g_h_hi[2][BB * HH];
__device__ __nv_bfloat16 g_h_lo[2][BB * HH];
__device__ float         g_c[BB * HH];
__device__ __nv_bfloat16 g_Wo_hi[OO * HH];
__device__ __nv_bfloat16 g_Wo_lo[OO * HH];

// ---------------- shared memory tiling ----------------
struct STiles {
    __nv_bfloat16 Ah[2][32][36];
    __nv_bfloat16 Al[2][32][36];
    __nv_bfloat16 Bh[2][128][36];
    __nv_bfloat16 Bl[2][128][36];
};
union SU {
    STiles t;
    float z[32][132];
};

__device__ __forceinline__ void mma_bf16(float (&c)[4],
                                         uint32_t a0, uint32_t a1, uint32_t a2, uint32_t a3,
                                         uint32_t b0, uint32_t b1) {
    asm volatile(
        "mma.sync.aligned.m16n8k16.row.col.f32.bf16.bf16.f32 "
        "{%0,%1,%2,%3}, {%4,%5,%6,%7}, {%8,%9}, {%0,%1,%2,%3};\n"
        : "+f"(c[0]), "+f"(c[1]), "+f"(c[2]), "+f"(c[3])
        : "r"(a0), "r"(a1), "r"(a2), "r"(a3), "r"(b0), "r"(b1));
}

__device__ __forceinline__ float sigmoidf_(float x) { return 1.f / (1.f + __expf(-x)); }
__device__ __forceinline__ float tanhf_(float x) { return 1.f - 2.f / (__expf(2.f * x) + 1.f); }

// ---------------- prep kernels ----------------
__global__ void prep_weights(const float* __restrict__ eWih, const float* __restrict__ eWhh,
                             const float* __restrict__ ebih, const float* __restrict__ ebhh,
                             const float* __restrict__ dWih, const float* __restrict__ dWhh,
                             const float* __restrict__ dbih, const float* __restrict__ dbhh,
                             const float* __restrict__ outW) {
    int idx = blockIdx.x * blockDim.x + threadIdx.x;
    int stride = gridDim.x * blockDim.x;
    // recurrent+input weights, gate-interleaved rows: jr = col*4 + gate
    for (int i = idx; i < 2 * G4 * KHX; i += stride) {
        int sel = i / (G4 * KHX);
        int r = i - sel * (G4 * KHX);
        int jr = r / KHX;
        int k = r - jr * KHX;
        int gate = jr & 3, col = jr >> 2;
        int js = gate * HH + col;
        const float* Wih = sel ? dWih : eWih;
        const float* Whh = sel ? dWhh : eWhh;
        float w = (k < HH) ? Whh[js * HH + k] : Wih[js * DD + (k - HH)];
        __nv_bfloat16 hi = __float2bfloat16(w);
        g_W_hi[sel][jr * KHX + k] = hi;
        g_W_lo[sel][jr * KHX + k] = __float2bfloat16(w - __bfloat162float(hi));
    }
    for (int i = idx; i < 2 * G4; i += stride) {
        int sel = i >> 11;
        int jr = i & (G4 - 1);
        int gate = jr & 3, col = jr >> 2;
        int js = gate * HH + col;
        g_bias[sel][jr] = sel ? (dbih[js] + dbhh[js]) : (ebih[js] + ebhh[js]);
    }
    for (int i = idx; i < OO * HH; i += stride) {
        float w = outW[i];
        __nv_bfloat16 hi = __float2bfloat16(w);
        g_Wo_hi[i] = hi;
        g_Wo_lo[i] = __float2bfloat16(w - __bfloat162float(hi));
    }
}

__global__ void prep_x(const float* __restrict__ enc, const float* __restrict__ dec) {
    int idx = blockIdx.x * blockDim.x + threadIdx.x;
    int stride = gridDim.x * blockDim.x;
    const int total = (TENC + TDEC) * BB * DD;
    for (int i = idx; i < total; i += stride) {
        int t = i / (BB * DD);
        int r = i - t * (BB * DD);
        int b = r / DD;
        int d = r - b * DD;
        float v = (t < TENC) ? enc[(b * TENC + t) * DD + d]
                             : dec[(b * TDEC + (t - TENC)) * DD + d];
        __nv_bfloat16 hi = __float2bfloat16(v);
        g_x_hi[i] = hi;
        g_x_lo[i] = __float2bfloat16(v - __bfloat162float(hi));
    }
}

__global__ void init_state() {
    int idx = blockIdx.x * blockDim.x + threadIdx.x;
    int stride = gridDim.x * blockDim.x;
    for (int i = idx; i < BB * HH; i += stride) {
        __nv_bfloat16 z = __float2bfloat16(0.f);
        g_h_hi[0][i] = z; g_h_hi[1][i] = z;
        g_h_lo[0][i] = z; g_h_lo[1][i] = z;
        g_c[i] = 0.f;
    }
}

// ---------------- per-step fused LSTM kernel ----------------
// grid: (16 col-blocks, 8 batch-blocks); block: 256 threads (8 warps: 2 along M x 4 along N)
// CTA tile: M=32 batch rows, N=128 gate-rows (= 32 h-cols x 4 gates), K=576
__global__ __launch_bounds__(256) void lstm_step_kernel(int sel, int xofs, int rp,
                                                        float* __restrict__ hid_out) {
    __shared__ SU su;
    const int tid = threadIdx.x;
    const int lane = tid & 31;
    const int warp = tid >> 5;
    const int wm = (warp & 1) * 16;
    const int wn = (warp >> 1) * 32;
    const int b0 = blockIdx.y * 32;
    const int j0 = blockIdx.x * 128;

    float acc[4][4];
#pragma unroll
    for (int s = 0; s < 4; ++s)
#pragma unroll
        for (int i = 0; i < 4; ++i) acc[s][i] = 0.f;

    // ---- load chunk 0 directly (always from h) ----
#pragma unroll
    for (int j = 0; j < 2; ++j) {
        int i = tid + j * 256;
        int row = i >> 4, k2 = (i & 15) * 2;
        int off = (b0 + row) * HH + k2;
        *(uint32_t*)&su.t.Ah[0][row][k2] = *(const uint32_t*)(g_h_hi[rp] + off);
        *(uint32_t*)&su.t.Al[0][row][k2] = *(const uint32_t*)(g_h_lo[rp] + off);
    }
#pragma unroll
    for (int j = 0; j < 8; ++j) {
        int i = tid + j * 256;
        int row = i >> 4, k2 = (i & 15) * 2;
        int off = (j0 + row) * KHX + k2;
        *(uint32_t*)&su.t.Bh[0][row][k2] = *(const uint32_t*)(g_W_hi[sel] + off);
        *(uint32_t*)&su.t.Bl[0][row][k2] = *(const uint32_t*)(g_W_lo[sel] + off);
    }

    uint32_t pAh[2], pAl[2], pBh[8], pBl[8];

    for (int kc = 0; kc < NCH; ++kc) {
        __syncthreads();
        const int q = kc & 1;

        if (kc + 1 < NCH) {
            const int kn = kc + 1;
#pragma unroll
            for (int j = 0; j < 2; ++j) {
                int i = tid + j * 256;
                int row = i >> 4, k2 = (i & 15) * 2;
                const __nv_bfloat16 *sh, *sl;
                if (kn < 16) {
                    int off = (b0 + row) * HH + kn * 32 + k2;
                    sh = g_h_hi[rp] + off; sl = g_h_lo[rp] + off;
                } else {
                    int off = xofs + (b0 + row) * DD + (kn - 16) * 32 + k2;
                    sh = g_x_hi + off; sl = g_x_lo + off;
                }
                pAh[j] = *(const uint32_t*)sh;
                pAl[j] = *(const uint32_t*)sl;
            }
#pragma unroll
            for (int j = 0; j < 8; ++j) {
                int i = tid + j * 256;
                int row = i >> 4, k2 = (i & 15) * 2;
                int off = (j0 + row) * KHX + kn * 32 + k2;
                pBh[j] = *(const uint32_t*)(g_W_hi[sel] + off);
                pBl[j] = *(const uint32_t*)(g_W_lo[sel] + off);
            }
        }

        // ---- compute on buffer q ----
#pragma unroll
        for (int k16 = 0; k16 < 2; ++k16) {
            const int ar = wm + (lane >> 2);
            const int ac = (lane & 3) * 2 + k16 * 16;
            uint32_t ah0 = *(const uint32_t*)&su.t.Ah[q][ar][ac];
            uint32_t ah1 = *(const uint32_t*)&su.t.Ah[q][ar + 8][ac];
            uint32_t ah2 = *(const uint32_t*)&su.t.Ah[q][ar][ac + 8];
            uint32_t ah3 = *(const uint32_t*)&su.t.Ah[q][ar + 8][ac + 8];
            uint32_t al0 = *(const uint32_t*)&su.t.Al[q][ar][ac];
            uint32_t al1 = *(const uint32_t*)&su.t.Al[q][ar + 8][ac];
            uint32_t al2 = *(const uint32_t*)&su.t.Al[q][ar][ac + 8];
            uint32_t al3 = *(const uint32_t*)&su.t.Al[q][ar + 8][ac + 8];
#pragma unroll
            for (int s = 0; s < 4; ++s) {
                const int br = wn + s * 8 + (lane >> 2);
                const int bc = (lane & 3) * 2 + k16 * 16;
                uint32_t bh0 = *(const uint32_t*)&su.t.Bh[q][br][bc];
                uint32_t bh1 = *(const uint32_t*)&su.t.Bh[q][br][bc + 8];
                uint32_t bl0 = *(const uint32_t*)&su.t.Bl[q][br][bc];
                uint32_t bl1 = *(const uint32_t*)&su.t.Bl[q][br][bc + 8];
                mma_bf16(acc[s], ah0, ah1, ah2, ah3, bh0, bh1);
                mma_bf16(acc[s], ah0, ah1, ah2, ah3, bl0, bl1);
                mma_bf16(acc[s], al0, al1, al2, al3, bh0, bh1);
            }
        }

        if (kc + 1 < NCH) {
            const int qn = q ^ 1;
#pragma unroll
            for (int j = 0; j < 2; ++j) {
                int i = tid + j * 256;
                int row = i >> 4, k2 = (i & 15) * 2;
                *(uint32_t*)&su.t.Ah[qn][row][k2] = pAh[j];
                *(uint32_t*)&su.t.Al[qn][row][k2] = pAl[j];
            }
#pragma unroll
            for (int j = 0; j < 8; ++j) {
                int i = tid + j * 256;
                int row = i >> 4, k2 = (i & 15) * 2;
                *(uint32_t*)&su.t.Bh[qn][row][k2] = pBh[j];
                *(uint32_t*)&su.t.Bl[qn][row][k2] = pBl[j];
            }
        }
    }

    // ---- stage z through smem (aliases the tile buffers) ----
    __syncthreads();
#pragma unroll
    for (int s = 0; s < 4; ++s) {
        const int r = wm + (lane >> 2);
        const int cc = wn + s * 8 + (lane & 3) * 2;
        su.z[r][cc]         = acc[s][0];
        su.z[r][cc + 1]     = acc[s][1];
        su.z[r + 8][cc]     = acc[s][2];
        su.z[r + 8][cc + 1] = acc[s][3];
    }
    __syncthreads();

    // ---- fused LSTM cell epilogue ----
    const float* bias = g_bias[sel] + j0;
    const int wp = rp ^ 1;
    const int c0 = j0 >> 2;  // global h-column base of this CTA
    for (int e = tid; e < 1024; e += 256) {
        int bl = e >> 5, cl = e & 31;
        float zi = su.z[bl][cl * 4 + 0] + bias[cl * 4 + 0];
        float zf = su.z[bl][cl * 4 + 1] + bias[cl * 4 + 1];
        float zg = su.z[bl][cl * 4 + 2] + bias[cl * 4 + 2];
        float zo = su.z[bl][cl * 4 + 3] + bias[cl * 4 + 3];
        int ci = (b0 + bl) * HH + c0 + cl;
        float cOld = g_c[ci];
        float ig = sigmoidf_(zi);
        float fg = sigmoidf_(zf);
        float gg = tanhf_(zg);
        float og = sigmoidf_(zo);
        float cN = fg * cOld + ig * gg;
        float hN = og * tanhf_(cN);
        g_c[ci] = cN;
        __nv_bfloat16 hh = __float2bfloat16(hN);
        g_h_hi[wp][ci] = hh;
        g_h_lo[wp][ci] = __float2bfloat16(hN - __bfloat162float(hh));
        if (hid_out) hid_out[(b0 + bl) * (TDEC * HH) + c0 + cl] = hN;
    }
}

// ---------------- final output projection: y = dec_h @ out_W^T + out_b ----------------
// grid: (4 n-blocks, 512 m-blocks); CTA tile 32x128, K=512
__global__ __launch_bounds__(256) void proj_kernel(const float* __restrict__ hid,
                                                   const float* __restrict__ outb,
                                                   float* __restrict__ out) {
    __shared__ SU su;
    const int tid = threadIdx.x;
    const int lane = tid & 31;
    const int warp = tid >> 5;
    const int wm = (warp & 1) * 16;
    const int wn = (warp >> 1) * 32;
    const int m0 = blockIdx.y * 32;
    const int n0 = blockIdx.x * 128;

    float acc[4][4];
#pragma unroll
    for (int s = 0; s < 4; ++s)
#pragma unroll
        for (int i = 0; i < 4; ++i) acc[s][i] = 0.f;

    // chunk 0 direct
#pragma unroll
    for (int j = 0; j < 4; ++j) {
        int i = tid + j * 256;
        int row = i >> 5, k = i & 31;
        float v = hid[(m0 + row) * HH + k];
        __nv_bfloat16 hi = __float2bfloat16(v);
        su.t.Ah[0][row][k] = hi;
        su.t.Al[0][row][k] = __float2bfloat16(v - __bfloat162float(hi));
    }
#pragma unroll
    for (int j = 0; j < 8; ++j) {
        int i = tid + j * 256;
        int row = i >> 4, k2 = (i & 15) * 2;
        int off = (n0 + row) * HH + k2;
        *(uint32_t*)&su.t.Bh[0][row][k2] = *(const uint32_t*)(g_Wo_hi + off);
        *(uint32_t*)&su.t.Bl[0][row][k2] = *(const uint32_t*)(g_Wo_lo + off);
    }

    float pv[4];
    uint32_t pBh[8], pBl[8];
    const int NCHP = HH / 32;  // 16

    for (int kc = 0; kc < NCHP; ++kc) {
        __syncthreads();
        const int q = kc & 1;
        if (kc + 1 < NCHP) {
            const int kn = kc + 1;
#pragma unroll
            for (int j = 0; j < 4; ++j) {
                int i = tid + j * 256;
                int row = i >> 5, k = i & 31;
                pv[j] = hid[(m0 + row) * HH + kn * 32 + k];
            }
#pragma unroll
            for (int j = 0; j < 8; ++j) {
                int i = tid + j * 256;
                int row = i >> 4, k2 = (i & 15) * 2;
                int off = (n0 + row) * HH + kn * 32 + k2;
                pBh[j] = *(const uint32_t*)(g_Wo_hi + off);
                pBl[j] = *(const uint32_t*)(g_Wo_lo + off);
            }
        }
#pragma unroll
        for (int k16 = 0; k16 < 2; ++k16) {
            const int ar = wm + (lane >> 2);
            const int ac = (lane & 3) * 2 + k16 * 16;
            uint32_t ah0 = *(const uint32_t*)&su.t.Ah[q][ar][ac];
            uint32_t ah1 = *(const uint32_t*)&su.t.Ah[q][ar + 8][ac];
            uint32_t ah2 = *(const uint32_t*)&su.t.Ah[q][ar][ac + 8];
            uint32_t ah3 = *(const uint32_t*)&su.t.Ah[q][ar + 8][ac + 8];
            uint32_t al0 = *(const uint32_t*)&su.t.Al[q][ar][ac];
            uint32_t al1 = *(const uint32_t*)&su.t.Al[q][ar + 8][ac];
            uint32_t al2 = *(const uint32_t*)&su.t.Al[q][ar][ac + 8];
            uint32_t al3 = *(const uint32_t*)&su.t.Al[q][ar + 8][ac + 8];
#pragma unroll
            for (int s = 0; s < 4; ++s) {
                const int br = wn + s * 8 + (lane >> 2);
                const int bc = (lane & 3) * 2 + k16 * 16;
                uint32_t bh0 = *(const uint32_t*)&su.t.Bh[q][br][bc];
                uint32_t bh1 = *(const uint32_t*)&su.t.Bh[q][br][bc + 8];
                uint32_t bl0 = *(const uint32_t*)&su.t.Bl[q][br][bc];
                uint32_t bl1 = *(const uint32_t*)&su.t.Bl[q][br][bc + 8];
                mma_bf16(acc[s], ah0, ah1, ah2, ah3, bh0, bh1);
                mma_bf16(acc[s], ah0, ah1, ah2, ah3, bl0, bl1);
                mma_bf16(acc[s], al0, al1, al2, al3, bh0, bh1);
            }
        }
        if (kc + 1 < NCHP) {
            const int qn = q ^ 1;
#pragma unroll
            for (int j = 0; j < 4; ++j) {
                int i = tid + j * 256;
                int row = i >> 5, k = i & 31;
                __nv_bfloat16 hi = __float2bfloat16(pv[j]);
                su.t.Ah[qn][row][k] = hi;
                su.t.Al[qn][row][k] = __float2bfloat16(pv[j] - __bfloat162float(hi));
            }
#pragma unroll
            for (int j = 0; j < 8; ++j) {
                int i = tid + j * 256;
                int row = i >> 4, k2 = (i & 15) * 2;
                *(uint32_t*)&su.t.Bh[qn][row][k2] = pBh[j];
                *(uint32_t*)&su.t.Bl[qn][row][k2] = pBl[j];
            }
        }
    }

    // epilogue: bias add + store
#pragma unroll
    for (int s = 0; s < 4; ++s) {
        const int r = m0 + wm + (lane >> 2);
        const int cc = n0 + wn + s * 8 + (lane & 3) * 2;
        out[(size_t)r * OO + cc]           = acc[s][0] + outb[cc];
        out[(size_t)r * OO + cc + 1]       = acc[s][1] + outb[cc + 1];
        out[(size_t)(r + 8) * OO + cc]     = acc[s][2] + outb[cc];
        out[(size_t)(r + 8) * OO + cc + 1] = acc[s][3] + outb[cc + 1];
    }
}

// ---------------- launch ----------------
extern "C" void kernel_launch(void* const* d_in, const int* in_sizes, int n_in,
                              void* d_out, int out_size) {
    const float* enc_inp = (const float*)d_in[0];
    const float* dec_inp = (const float*)d_in[1];
    const float* eWih = (const float*)d_in[2];
    const float* eWhh = (const float*)d_in[3];
    const float* ebih = (const float*)d_in[4];
    const float* ebhh = (const float*)d_in[5];
    const float* dWih = (const float*)d_in[6];
    const float* dWhh = (const float*)d_in[7];
    const float* dbih = (const float*)d_in[8];
    const float* dbhh = (const float*)d_in[9];
    const float* outW = (const float*)d_in[10];
    const float* outb = (const float*)d_in[11];
    float* out = (float*)d_out;

    prep_weights<<<256, 256>>>(eWih, eWhh, ebih, ebhh, dWih, dWhh, dbih, dbhh, outW);
    prep_x<<<2048, 256>>>(enc_inp, dec_inp);
    init_state<<<512, 256>>>();

    dim3 grid(16, 8);
    // encoder: 512 steps
    for (int t = 0; t < TENC; ++t) {
        lstm_step_kernel<<<grid, 256>>>(0, t * BB * DD, t & 1, nullptr);
    }
    // decoder: 64 steps, writing dec_hiddens (fp32) into the tail of d_out
    float* hid_base = out + OUT_OFS;
    for (int s = 0; s < TDEC; ++s) {
        lstm_step_kernel<<<grid, 256>>>(1, (TENC + s) * BB * DD, s & 1, hid_base + s * HH);
    }
    // output projection over all decoder hiddens
    proj_kernel<<<dim3(4, 512), 256>>>(hid_base, outb, out);
}

// round 3
// speedup vs baseline: 1.7965x; 1.7965x over previous
#include <cuda_runtime.h>
#include <cuda_bf16.h>
#include <cstdint>

#define BB 256
#define TENC 512
#define TDEC 64
#define DD 64
#define HH 512
#define OO 512
#define G4 2048            // 4*H
#define KHX 576            // H + D
#define NCH 18             // KHX / 32
#define OUT_OFS ((size_t)BB * TDEC * OO)

// ---------------- device-global scratch ----------------
__device__ __align__(16) __nv_bfloat16 g_W_hi[2][G4 * KHX];
__device__ __align__(16) __nv_bfloat16 g_W_lo[2][G4 * KHX];
__device__ __align__(16) float         g_bias[2][G4];
__device__ __align__(16) __nv_bfloat16 g_x_hi[(TENC + TDEC) * BB * DD];
__device__ __align__(16) __nv_bfloat16 g_x_lo[(TENC + TDEC) * BB * DD];
__device__ __align__(16) __nv_bfloat16 g_h_hi[2][BB * HH];
__device__ __align__(16) __nv_bfloat16 g_h_lo[2][BB * HH];
__device__ __align__(16) float         g_c[BB * HH];
__device__ __align__(16) __nv_bfloat16 g_Wo_hi[OO * HH];
__device__ __align__(16) __nv_bfloat16 g_Wo_lo[OO * HH];

// ---------------- small helpers ----------------
__device__ __forceinline__ void mma_bf16(float (&c)[4],
                                         uint32_t a0, uint32_t a1, uint32_t a2, uint32_t a3,
                                         uint32_t b0, uint32_t b1) {
    asm volatile(
        "mma.sync.aligned.m16n8k16.row.col.f32.bf16.bf16.f32 "
        "{%0,%1,%2,%3}, {%4,%5,%6,%7}, {%8,%9}, {%0,%1,%2,%3};\n"
        : "+f"(c[0]), "+f"(c[1]), "+f"(c[2]), "+f"(c[3])
        : "r"(a0), "r"(a1), "r"(a2), "r"(a3), "r"(b0), "r"(b1));
}

__device__ __forceinline__ void ldsm4(uint32_t* r, uint32_t addr) {
    asm volatile("ldmatrix.sync.aligned.m8n8.x4.shared.b16 {%0,%1,%2,%3}, [%4];\n"
                 : "=r"(r[0]), "=r"(r[1]), "=r"(r[2]), "=r"(r[3]) : "r"(addr));
}

__device__ __forceinline__ void cp16(uint32_t dst, const void* src) {
    asm volatile("cp.async.cg.shared.global [%0], [%1], 16;\n" :: "r"(dst), "l"(src));
}
__device__ __forceinline__ void cp_commit() { asm volatile("cp.async.commit_group;\n"); }
template <int N> __device__ __forceinline__ void cp_wait() {
    asm volatile("cp.async.wait_group %0;\n" :: "n"(N));
}

__device__ __forceinline__ float sigmoidf_(float x) { return 1.f / (1.f + __expf(-x)); }
__device__ __forceinline__ float tanhf_(float x) { return 1.f - 2.f / (__expf(2.f * x) + 1.f); }

// ---------------- prep kernels ----------------
__global__ void prep_weights(const float* __restrict__ eWih, const float* __restrict__ eWhh,
                             const float* __restrict__ ebih, const float* __restrict__ ebhh,
                             const float* __restrict__ dWih, const float* __restrict__ dWhh,
                             const float* __restrict__ dbih, const float* __restrict__ dbhh,
                             const float* __restrict__ outW) {
    int idx = blockIdx.x * blockDim.x + threadIdx.x;
    int stride = gridDim.x * blockDim.x;
    for (int i = idx; i < 2 * G4 * KHX; i += stride) {
        int sel = i / (G4 * KHX);
        int r = i - sel * (G4 * KHX);
        int jr = r / KHX;
        int k = r - jr * KHX;
        int gate = jr & 3, col = jr >> 2;
        int js = gate * HH + col;
        const float* Wih = sel ? dWih : eWih;
        const float* Whh = sel ? dWhh : eWhh;
        float w = (k < HH) ? Whh[js * HH + k] : Wih[js * DD + (k - HH)];
        __nv_bfloat16 hi = __float2bfloat16(w);
        g_W_hi[sel][jr * KHX + k] = hi;
        g_W_lo[sel][jr * KHX + k] = __float2bfloat16(w - __bfloat162float(hi));
    }
    for (int i = idx; i < 2 * G4; i += stride) {
        int sel = i >> 11;
        int jr = i & (G4 - 1);
        int gate = jr & 3, col = jr >> 2;
        int js = gate * HH + col;
        g_bias[sel][jr] = sel ? (dbih[js] + dbhh[js]) : (ebih[js] + ebhh[js]);
    }
    for (int i = idx; i < OO * HH; i += stride) {
        float w = outW[i];
        __nv_bfloat16 hi = __float2bfloat16(w);
        g_Wo_hi[i] = hi;
        g_Wo_lo[i] = __float2bfloat16(w - __bfloat162float(hi));
    }
}

__global__ void prep_x(const float* __restrict__ enc, const float* __restrict__ dec) {
    int idx = blockIdx.x * blockDim.x + threadIdx.x;
    int stride = gridDim.x * blockDim.x;
    const int total = (TENC + TDEC) * BB * DD;
    for (int i = idx; i < total; i += stride) {
        int t = i / (BB * DD);
        int r = i - t * (BB * DD);
        int b = r / DD;
        int d = r - b * DD;
        float v = (t < TENC) ? enc[(b * TENC + t) * DD + d]
                             : dec[(b * TDEC + (t - TENC)) * DD + d];
        __nv_bfloat16 hi = __float2bfloat16(v);
        g_x_hi[i] = hi;
        g_x_lo[i] = __float2bfloat16(v - __bfloat162float(hi));
    }
}

__global__ void init_state() {
    int idx = blockIdx.x * blockDim.x + threadIdx.x;
    int stride = gridDim.x * blockDim.x;
    for (int i = idx; i < BB * HH; i += stride) {
        __nv_bfloat16 z = __float2bfloat16(0.f);
        g_h_hi[0][i] = z; g_h_hi[1][i] = z;
        g_h_lo[0][i] = z; g_h_lo[1][i] = z;
        g_c[i] = 0.f;
    }
}

// ---------------- per-step fused LSTM kernel ----------------
// grid (16, 8); 512 threads = 16 warps: kw(2) x mw(2) x nw(4)
// CTA tile: M=32 batch, N=128 gate-rows, K=576 in 18 chunks of 32 (kw splits chunk into k16 halves)
// 3-stage cp.async pipeline; dynamic smem:
//   stage s (25600B): Ah[32][40] @0, Al @2560, Bh[128][40] @5120, Bl @15360
#define STG 25600
#define A_LO_OFS 2560
#define B_HI_OFS 5120
#define B_LO_OFS 15360
#define SMEM_DYN (3 * STG)

__global__ __launch_bounds__(512, 1) void lstm_step_kernel(int sel, int xofs, int rp,
                                                           float* __restrict__ hid_out) {
    extern __shared__ __align__(16) char sm[];
    const uint32_t sbase = (uint32_t)__cvta_generic_to_shared(sm);
    const int tid = threadIdx.x;
    const int lane = tid & 31;
    const int warp = tid >> 5;
    const int nw = warp & 3;
    const int mw = (warp >> 2) & 1;
    const int kw = warp >> 3;
    const int b0 = blockIdx.y * 32;
    const int j0 = blockIdx.x * 128;

    float acc[4][4];
#pragma unroll
    for (int f = 0; f < 4; ++f)
#pragma unroll
        for (int i = 0; i < 4; ++i) acc[f][i] = 0.f;

    // fragment addressing (stage-independent parts)
    const int fr = (lane & 7) + ((lane >> 3) & 1) * 8;   // row within 16
    const int fc = kw * 16 + ((lane >> 3) >> 1) * 8;     // col (k) within 32

    auto issue = [&](int kc) {
        uint32_t st = sbase + (uint32_t)((kc % 3) * STG);
        if (tid < 256) {
            int selA = tid >> 7, row = (tid >> 2) & 31, c = tid & 3;
            uint32_t dst = st + (selA ? A_LO_OFS : 0) + row * 80 + c * 16;
            const __nv_bfloat16* src;
            if (kc < 16) {
                const __nv_bfloat16* base = selA ? g_h_lo[rp] : g_h_hi[rp];
                src = base + (b0 + row) * HH + kc * 32 + c * 8;
            } else {
                const __nv_bfloat16* base = selA ? g_x_lo : g_x_hi;
                src = base + xofs + (b0 + row) * DD + (kc - 16) * 32 + c * 8;
            }
            cp16(dst, src);
        }
#pragma unroll
        for (int j = 0; j < 2; ++j) {
            int i = tid + j * 512;
            int selB = i >> 9, row = (i >> 2) & 127, c = i & 3;
            uint32_t dst = st + (selB ? B_LO_OFS : B_HI_OFS) + row * 80 + c * 16;
            const __nv_bfloat16* base = selB ? g_W_lo[sel] : g_W_hi[sel];
            cp16(dst, base + (j0 + row) * KHX + kc * 32 + c * 8);
        }
    };

    auto compute = [&](int s) {
        uint32_t st = sbase + (uint32_t)(s * STG);
        uint32_t ah[4], al[4], bh[8], bl[8];
        uint32_t aaddr = st + (mw * 16 + fr) * 80 + fc * 2;
        ldsm4(ah, aaddr);
        ldsm4(al, aaddr + A_LO_OFS);
#pragma unroll
        for (int g = 0; g < 2; ++g) {
            uint32_t baddr = st + B_HI_OFS + (nw * 32 + g * 16 + fr) * 80 + fc * 2;
            ldsm4(&bh[g * 4], baddr);
            ldsm4(&bl[g * 4], baddr + (B_LO_OFS - B_HI_OFS));
        }
#pragma unroll
        for (int f = 0; f < 4; ++f) {
            uint32_t b0h = bh[(f >> 1) * 4 + (f & 1)];
            uint32_t b1h = bh[(f >> 1) * 4 + 2 + (f & 1)];
            uint32_t b0l = bl[(f >> 1) * 4 + (f & 1)];
            uint32_t b1l = bl[(f >> 1) * 4 + 2 + (f & 1)];
            mma_bf16(acc[f], ah[0], ah[1], ah[2], ah[3], b0h, b1h);
            mma_bf16(acc[f], ah[0], ah[1], ah[2], ah[3], b0l, b1l);
            mma_bf16(acc[f], al[0], al[1], al[2], al[3], b0h, b1h);
        }
    };

    issue(0); cp_commit();
    issue(1); cp_commit();

    for (int kc = 0; kc < NCH; ++kc) {
        cp_wait<1>();
        __syncthreads();
        if (kc + 2 < NCH) issue(kc + 2);
        cp_commit();
        compute(kc % 3);
    }
    __syncthreads();

    // ---- cross-kw reduction through smem (alias stage buffers) ----
    float* z = (float*)sm;   // z[32][132]
    const int zr = mw * 16 + (lane >> 2);
    if (kw == 1) {
#pragma unroll
        for (int f = 0; f < 4; ++f) {
            int c = nw * 32 + f * 8 + (lane & 3) * 2;
            z[zr * 132 + c]           = acc[f][0];
            z[zr * 132 + c + 1]       = acc[f][1];
            z[(zr + 8) * 132 + c]     = acc[f][2];
            z[(zr + 8) * 132 + c + 1] = acc[f][3];
        }
    }
    __syncthreads();
    if (kw == 0) {
#pragma unroll
        for (int f = 0; f < 4; ++f) {
            int c = nw * 32 + f * 8 + (lane & 3) * 2;
            z[zr * 132 + c]           += acc[f][0];
            z[zr * 132 + c + 1]       += acc[f][1];
            z[(zr + 8) * 132 + c]     += acc[f][2];
            z[(zr + 8) * 132 + c + 1] += acc[f][3];
        }
    }
    __syncthreads();

    // ---- fused LSTM cell epilogue ----
    const float* bias = g_bias[sel] + j0;
    const int wp = rp ^ 1;
    const int c0 = j0 >> 2;
    for (int e = tid; e < 1024; e += 512) {
        int bl_ = e >> 5, cl = e & 31;
        float zi = z[bl_ * 132 + cl * 4 + 0] + bias[cl * 4 + 0];
        float zf = z[bl_ * 132 + cl * 4 + 1] + bias[cl * 4 + 1];
        float zg = z[bl_ * 132 + cl * 4 + 2] + bias[cl * 4 + 2];
        float zo = z[bl_ * 132 + cl * 4 + 3] + bias[cl * 4 + 3];
        int ci = (b0 + bl_) * HH + c0 + cl;
        float cOld = g_c[ci];
        float ig = sigmoidf_(zi);
        float fg = sigmoidf_(zf);
        float gg = tanhf_(zg);
        float og = sigmoidf_(zo);
        float cN = fg * cOld + ig * gg;
        float hN = og * tanhf_(cN);
        g_c[ci] = cN;
        __nv_bfloat16 hh = __float2bfloat16(hN);
        g_h_hi[wp][ci] = hh;
        g_h_lo[wp][ci] = __float2bfloat16(hN - __bfloat162float(hh));
        if (hid_out) hid_out[(b0 + bl_) * (TDEC * HH) + c0 + cl] = hN;
    }
}

// ---------------- final output projection (unchanged from R1) ----------------
struct STiles {
    __nv_bfloat16 Ah[2][32][36];
    __nv_bfloat16 Al[2][32][36];
    __nv_bfloat16 Bh[2][128][36];
    __nv_bfloat16 Bl[2][128][36];
};
union SU {
    STiles t;
    float z[32][132];
};

__global__ __launch_bounds__(256) void proj_kernel(const float* __restrict__ hid,
                                                   const float* __restrict__ outb,
                                                   float* __restrict__ out) {
    __shared__ SU su;
    const int tid = threadIdx.x;
    const int lane = tid & 31;
    const int warp = tid >> 5;
    const int wm = (warp & 1) * 16;
    const int wn = (warp >> 1) * 32;
    const int m0 = blockIdx.y * 32;
    const int n0 = blockIdx.x * 128;

    float acc[4][4];
#pragma unroll
    for (int s = 0; s < 4; ++s)
#pragma unroll
        for (int i = 0; i < 4; ++i) acc[s][i] = 0.f;

#pragma unroll
    for (int j = 0; j < 4; ++j) {
        int i = tid + j * 256;
        int row = i >> 5, k = i & 31;
        float v = hid[(m0 + row) * HH + k];
        __nv_bfloat16 hi = __float2bfloat16(v);
        su.t.Ah[0][row][k] = hi;
        su.t.Al[0][row][k] = __float2bfloat16(v - __bfloat162float(hi));
    }
#pragma unroll
    for (int j = 0; j < 8; ++j) {
        int i = tid + j * 256;
        int row = i >> 4, k2 = (i & 15) * 2;
        int off = (n0 + row) * HH + k2;
        *(uint32_t*)&su.t.Bh[0][row][k2] = *(const uint32_t*)(g_Wo_hi + off);
        *(uint32_t*)&su.t.Bl[0][row][k2] = *(const uint32_t*)(g_Wo_lo + off);
    }

    float pv[4];
    uint32_t pBh[8], pBl[8];
    const int NCHP = HH / 32;

    for (int kc = 0; kc < NCHP; ++kc) {
        __syncthreads();
        const int q = kc & 1;
        if (kc + 1 < NCHP) {
            const int kn = kc + 1;
#pragma unroll
            for (int j = 0; j < 4; ++j) {
                int i = tid + j * 256;
                int row = i >> 5, k = i & 31;
                pv[j] = hid[(m0 + row) * HH + kn * 32 + k];
            }
#pragma unroll
            for (int j = 0; j < 8; ++j) {
                int i = tid + j * 256;
                int row = i >> 4, k2 = (i & 15) * 2;
                int off = (n0 + row) * HH + kn * 32 + k2;
                pBh[j] = *(const uint32_t*)(g_Wo_hi + off);
                pBl[j] = *(const uint32_t*)(g_Wo_lo + off);
            }
        }
#pragma unroll
        for (int k16 = 0; k16 < 2; ++k16) {
            const int ar = wm + (lane >> 2);
            const int ac = (lane & 3) * 2 + k16 * 16;
            uint32_t ah0 = *(const uint32_t*)&su.t.Ah[q][ar][ac];
            uint32_t ah1 = *(const uint32_t*)&su.t.Ah[q][ar + 8][ac];
            uint32_t ah2 = *(const uint32_t*)&su.t.Ah[q][ar][ac + 8];
            uint32_t ah3 = *(const uint32_t*)&su.t.Ah[q][ar + 8][ac + 8];
            uint32_t al0 = *(const uint32_t*)&su.t.Al[q][ar][ac];
            uint32_t al1 = *(const uint32_t*)&su.t.Al[q][ar + 8][ac];
            uint32_t al2 = *(const uint32_t*)&su.t.Al[q][ar][ac + 8];
            uint32_t al3 = *(const uint32_t*)&su.t.Al[q][ar + 8][ac + 8];
#pragma unroll
            for (int s = 0; s < 4; ++s) {
                const int br = wn + s * 8 + (lane >> 2);
                const int bc = (lane & 3) * 2 + k16 * 16;
                uint32_t bh0 = *(const uint32_t*)&su.t.Bh[q][br][bc];
                uint32_t bh1 = *(const uint32_t*)&su.t.Bh[q][br][bc + 8];
                uint32_t bl0 = *(const uint32_t*)&su.t.Bl[q][br][bc];
                uint32_t bl1 = *(const uint32_t*)&su.t.Bl[q][br][bc + 8];
                mma_bf16(acc[s], ah0, ah1, ah2, ah3, bh0, bh1);
                mma_bf16(acc[s], ah0, ah1, ah2, ah3, bl0, bl1);
                mma_bf16(acc[s], al0, al1, al2, al3, bh0, bh1);
            }
        }
        if (kc + 1 < NCHP) {
            const int qn = q ^ 1;
#pragma unroll
            for (int j = 0; j < 4; ++j) {
                int i = tid + j * 256;
                int row = i >> 5, k = i & 31;
                __nv_bfloat16 hi = __float2bfloat16(pv[j]);
                su.t.Ah[qn][row][k] = hi;
                su.t.Al[qn][row][k] = __float2bfloat16(pv[j] - __bfloat162float(hi));
            }
#pragma unroll
            for (int j = 0; j < 8; ++j) {
                int i = tid + j * 256;
                int row = i >> 4, k2 = (i & 15) * 2;
                *(uint32_t*)&su.t.Bh[qn][row][k2] = pBh[j];
                *(uint32_t*)&su.t.Bl[qn][row][k2] = pBl[j];
            }
        }
    }

#pragma unroll
    for (int s = 0; s < 4; ++s) {
        const int r = m0 + wm + (lane >> 2);
        const int cc = n0 + wn + s * 8 + (lane & 3) * 2;
        out[(size_t)r * OO + cc]           = acc[s][0] + outb[cc];
        out[(size_t)r * OO + cc + 1]       = acc[s][1] + outb[cc + 1];
        out[(size_t)(r + 8) * OO + cc]     = acc[s][2] + outb[cc];
        out[(size_t)(r + 8) * OO + cc + 1] = acc[s][3] + outb[cc + 1];
    }
}

// ---------------- launch ----------------
extern "C" void kernel_launch(void* const* d_in, const int* in_sizes, int n_in,
                              void* d_out, int out_size) {
    const float* enc_inp = (const float*)d_in[0];
    const float* dec_inp = (const float*)d_in[1];
    const float* eWih = (const float*)d_in[2];
    const float* eWhh = (const float*)d_in[3];
    const float* ebih = (const float*)d_in[4];
    const float* ebhh = (const float*)d_in[5];
    const float* dWih = (const float*)d_in[6];
    const float* dWhh = (const float*)d_in[7];
    const float* dbih = (const float*)d_in[8];
    const float* dbhh = (const float*)d_in[9];
    const float* outW = (const float*)d_in[10];
    const float* outb = (const float*)d_in[11];
    float* out = (float*)d_out;

    cudaFuncSetAttribute(lstm_step_kernel, cudaFuncAttributeMaxDynamicSharedMemorySize,
                         SMEM_DYN);

    prep_weights<<<256, 256>>>(eWih, eWhh, ebih, ebhh, dWih, dWhh, dbih, dbhh, outW);
    prep_x<<<2048, 256>>>(enc_inp, dec_inp);
    init_state<<<512, 256>>>();

    dim3 grid(16, 8);
    for (int t = 0; t < TENC; ++t) {
        lstm_step_kernel<<<grid, 512, SMEM_DYN>>>(0, t * BB * DD, t & 1, nullptr);
    }
    float* hid_base = out + OUT_OFS;
    for (int s = 0; s < TDEC; ++s) {
        lstm_step_kernel<<<grid, 512, SMEM_DYN>>>(1, (TENC + s) * BB * DD, s & 1,
                                                  hid_base + s * HH);
    }
    proj_kernel<<<dim3(4, 512), 256>>>(hid_base, outb, out);
}

// round 4
// speedup vs baseline: 1.8211x; 1.0137x over previous
#include <cuda_runtime.h>
#include <cuda_bf16.h>
#include <cstdint>

#define BB 256
#define TENC 512
#define TDEC 64
#define TT (TENC + TDEC)
#define DD 64
#define HH 512
#define OO 512
#define G4 2048            // 4*H
#define KHX 576            // H + D
#define OUT_OFS ((size_t)BB * TDEC * OO)
#define NCTA 128

// smem layout (dynamic), bytes:
//  W_hi  @ 0       : 64 rows x 1168 B  (stride 584 bf16)  = 74752
//  W_lo  @ 74752   : same                                  -> 149504
//  A stages @ 149504, 3 x 18432:
//     stage: Ah[64][144B] (9216) then Al (9216)
//  z aliases stage0 region: float z[64][68]
#define WLO_OFS 74752u
#define ABASE   149504u
#define ASTG    18432u
#define SMEM_DYN 204800

// ---------------- device-global scratch ----------------
__device__ __align__(16) __nv_bfloat16 g_W_hi[2][G4 * KHX];
__device__ __align__(16) __nv_bfloat16 g_W_lo[2][G4 * KHX];
__device__ __align__(16) float         g_bias[2][G4];
__device__ __align__(16) __nv_bfloat16 g_x_hi[TT * BB * DD];
__device__ __align__(16) __nv_bfloat16 g_x_lo[TT * BB * DD];
__device__ __align__(16) __nv_bfloat16 g_h_hi[2][BB * HH];
__device__ __align__(16) __nv_bfloat16 g_h_lo[2][BB * HH];
__device__ __align__(16) __nv_bfloat16 g_Wo_hi[OO * HH];
__device__ __align__(16) __nv_bfloat16 g_Wo_lo[OO * HH];
__device__ unsigned g_bar_arrive;
__device__ unsigned g_bar_gen;

// ---------------- helpers ----------------
__device__ __forceinline__ void mma_bf16(float (&c)[4],
                                         uint32_t a0, uint32_t a1, uint32_t a2, uint32_t a3,
                                         uint32_t b0, uint32_t b1) {
    asm volatile(
        "mma.sync.aligned.m16n8k16.row.col.f32.bf16.bf16.f32 "
        "{%0,%1,%2,%3}, {%4,%5,%6,%7}, {%8,%9}, {%0,%1,%2,%3};\n"
        : "+f"(c[0]), "+f"(c[1]), "+f"(c[2]), "+f"(c[3])
        : "r"(a0), "r"(a1), "r"(a2), "r"(a3), "r"(b0), "r"(b1));
}

__device__ __forceinline__ void ldsm4(uint32_t* r, uint32_t addr) {
    asm volatile("ldmatrix.sync.aligned.m8n8.x4.shared.b16 {%0,%1,%2,%3}, [%4];\n"
                 : "=r"(r[0]), "=r"(r[1]), "=r"(r[2]), "=r"(r[3]) : "r"(addr));
}

__device__ __forceinline__ void cp16(uint32_t dst, const void* src) {
    asm volatile("cp.async.cg.shared.global [%0], [%1], 16;\n" :: "r"(dst), "l"(src));
}
__device__ __forceinline__ void cp_commit() { asm volatile("cp.async.commit_group;\n"); }
template <int N> __device__ __forceinline__ void cp_wait() {
    asm volatile("cp.async.wait_group %0;\n" :: "n"(N));
}

__device__ __forceinline__ float sigmoidf_(float x) { return 1.f / (1.f + __expf(-x)); }
__device__ __forceinline__ float tanhf_(float x) { return 1.f - 2.f / (__expf(2.f * x) + 1.f); }

// ---------------- prep kernels ----------------
__global__ void prep_weights(const float* __restrict__ eWih, const float* __restrict__ eWhh,
                             const float* __restrict__ ebih, const float* __restrict__ ebhh,
                             const float* __restrict__ dWih, const float* __restrict__ dWhh,
                             const float* __restrict__ dbih, const float* __restrict__ dbhh,
                             const float* __restrict__ outW) {
    int idx = blockIdx.x * blockDim.x + threadIdx.x;
    int stride = gridDim.x * blockDim.x;
    for (int i = idx; i < 2 * G4 * KHX; i += stride) {
        int sel = i / (G4 * KHX);
        int r = i - sel * (G4 * KHX);
        int jr = r / KHX;
        int k = r - jr * KHX;
        int gate = jr & 3, col = jr >> 2;
        int js = gate * HH + col;
        const float* Wih = sel ? dWih : eWih;
        const float* Whh = sel ? dWhh : eWhh;
        float w = (k < HH) ? Whh[js * HH + k] : Wih[js * DD + (k - HH)];
        __nv_bfloat16 hi = __float2bfloat16(w);
        g_W_hi[sel][jr * KHX + k] = hi;
        g_W_lo[sel][jr * KHX + k] = __float2bfloat16(w - __bfloat162float(hi));
    }
    for (int i = idx; i < 2 * G4; i += stride) {
        int sel = i >> 11;
        int jr = i & (G4 - 1);
        int gate = jr & 3, col = jr >> 2;
        int js = gate * HH + col;
        g_bias[sel][jr] = sel ? (dbih[js] + dbhh[js]) : (ebih[js] + ebhh[js]);
    }
    for (int i = idx; i < OO * HH; i += stride) {
        float w = outW[i];
        __nv_bfloat16 hi = __float2bfloat16(w);
        g_Wo_hi[i] = hi;
        g_Wo_lo[i] = __float2bfloat16(w - __bfloat162float(hi));
    }
}

__global__ void prep_x(const float* __restrict__ enc, const float* __restrict__ dec) {
    int idx = blockIdx.x * blockDim.x + threadIdx.x;
    int stride = gridDim.x * blockDim.x;
    const int total = TT * BB * DD;
    for (int i = idx; i < total; i += stride) {
        int t = i / (BB * DD);
        int r = i - t * (BB * DD);
        int b = r / DD;
        int d = r - b * DD;
        float v = (t < TENC) ? enc[(b * TENC + t) * DD + d]
                             : dec[(b * TDEC + (t - TENC)) * DD + d];
        __nv_bfloat16 hi = __float2bfloat16(v);
        g_x_hi[i] = hi;
        g_x_lo[i] = __float2bfloat16(v - __bfloat162float(hi));
    }
}

__global__ void init_state() {
    int idx = blockIdx.x * blockDim.x + threadIdx.x;
    int stride = gridDim.x * blockDim.x;
    if (idx == 0) { g_bar_arrive = 0; g_bar_gen = 0; }
    for (int i = idx; i < BB * HH; i += stride) {
        __nv_bfloat16 z = __float2bfloat16(0.f);
        g_h_hi[0][i] = z; g_h_hi[1][i] = z;
        g_h_lo[0][i] = z; g_h_lo[1][i] = z;
    }
}

// ---------------- persistent LSTM kernel ----------------
// grid (32 n-blocks, 4 m-blocks) = 128 CTAs; 512 threads = 16 warps: nw2 x mw2 x kw4
// CTA tile per step: M=64 batch x N=64 gate-rows x K=576 (9 chunks of k64; kw picks k16 in chunk)
__global__ __launch_bounds__(512, 1) void lstm_persist(float* __restrict__ hid_base) {
    extern __shared__ __align__(16) char sm[];
    const uint32_t sbase = (uint32_t)__cvta_generic_to_shared(sm);
    const int tid = threadIdx.x;
    const int lane = tid & 31;
    const int warp = tid >> 5;
    const int nw = warp & 1;
    const int mw = (warp >> 1) & 1;
    const int kw = warp >> 2;
    const int j0 = blockIdx.x * 64;   // gate-row base
    const int b0 = blockIdx.y * 64;   // batch base
    const int c0 = j0 >> 2;           // h-column base

    // one-time resident weight load (sel = 0/1)
    auto loadW = [&](int sel) {
        for (int i = tid; i < 9216; i += 512) {
            int s2 = (i >= 4608);
            int rem = s2 ? i - 4608 : i;
            int r = rem / 72, u = rem - r * 72;
            uint32_t dst = sbase + (s2 ? WLO_OFS : 0u) + r * 1168 + u * 16;
            const __nv_bfloat16* src =
                (s2 ? g_W_lo[sel] : g_W_hi[sel]) + (j0 + r) * KHX + u * 8;
            cp16(dst, src);
        }
        cp_commit();
        cp_wait<0>();
        __syncthreads();
    };
    loadW(0);

    // cell state resident in registers: thread owns elems e = tid, tid+512 of 64x16 tile
    float creg[2] = {0.f, 0.f};
    unsigned mygen = 0;

    // fragment addressing constants
    const int fr = lane & 15;
    const int fhalf = (lane >> 4) * 16;   // byte offset of k8 half

    float acc[2][4][4];

    for (int t = 0; t < TT; ++t) {
        const int p = t & 1;
        const int sel = (t >= TENC);
        const int xofs = t * BB * DD;
        if (t == TENC) loadW(1);

#pragma unroll
        for (int mi = 0; mi < 2; ++mi)
#pragma unroll
            for (int f = 0; f < 4; ++f)
#pragma unroll
                for (int e = 0; e < 4; ++e) acc[mi][f][e] = 0.f;

        auto issueA = [&](int c) {
            uint32_t st = sbase + ABASE + (uint32_t)((c % 3) * ASTG);
#pragma unroll
            for (int j = 0; j < 2; ++j) {
                int i = tid + j * 512;
                int selA = i >> 9;
                int r = (i >> 3) & 63;
                int u = i & 7;
                uint32_t dst = st + selA * 9216 + r * 144 + u * 16;
                const __nv_bfloat16* src;
                if (c < 8) {
                    src = (selA ? g_h_lo[p] : g_h_hi[p]) + (b0 + r) * HH + c * 64 + u * 8;
                } else {
                    src = (selA ? g_x_lo : g_x_hi) + xofs + (b0 + r) * DD + u * 8;
                }
                cp16(dst, src);
            }
        };

        auto compute = [&](int c) {
            uint32_t st = sbase + ABASE + (uint32_t)((c % 3) * ASTG);
            uint32_t ah[8], al[8], bh[8], bl[8];
            uint32_t aaddr = st + (mw * 32 + fr) * 144 + kw * 32 + fhalf;
            ldsm4(ah, aaddr);
            ldsm4(ah + 4, aaddr + 16 * 144);
            ldsm4(al, aaddr + 9216);
            ldsm4(al + 4, aaddr + 9216 + 16 * 144);
            uint32_t kb = (uint32_t)(c * 128 + kw * 32) + fhalf;
#pragma unroll
            for (int g = 0; g < 2; ++g) {
                uint32_t baddr = sbase + (nw * 32 + g * 16 + fr) * 1168 + kb;
                ldsm4(&bh[g * 4], baddr);
                ldsm4(&bl[g * 4], baddr + WLO_OFS);
            }
#pragma unroll
            for (int mi = 0; mi < 2; ++mi)
#pragma unroll
                for (int f = 0; f < 4; ++f) {
                    uint32_t b0h = bh[(f >> 1) * 4 + (f & 1)];
                    uint32_t b1h = bh[(f >> 1) * 4 + 2 + (f & 1)];
                    uint32_t b0l = bl[(f >> 1) * 4 + (f & 1)];
                    uint32_t b1l = bl[(f >> 1) * 4 + 2 + (f & 1)];
                    mma_bf16(acc[mi][f], ah[mi * 4], ah[mi * 4 + 1], ah[mi * 4 + 2],
                             ah[mi * 4 + 3], b0h, b1h);
                    mma_bf16(acc[mi][f], ah[mi * 4], ah[mi * 4 + 1], ah[mi * 4 + 2],
                             ah[mi * 4 + 3], b0l, b1l);
                    mma_bf16(acc[mi][f], al[mi * 4], al[mi * 4 + 1], al[mi * 4 + 2],
                             al[mi * 4 + 3], b0h, b1h);
                }
        };

        issueA(0); cp_commit();
        issueA(1); cp_commit();
        for (int c = 0; c < 9; ++c) {
            cp_wait<1>();
            __syncthreads();
            if (c + 2 < 9) issueA(c + 2);
            cp_commit();
            compute(c);
        }
        __syncthreads();

        // ---- kw reduction into z[64][68] (aliases stage0) ----
        float* z = (float*)(sm + ABASE);
        for (int w = 3; w >= 0; --w) {
            if (kw == w) {
#pragma unroll
                for (int mi = 0; mi < 2; ++mi)
#pragma unroll
                    for (int f = 0; f < 4; ++f) {
                        int zr = mw * 32 + mi * 16 + (lane >> 2);
                        int zc = nw * 32 + f * 8 + (lane & 3) * 2;
                        if (w == 3) {
                            z[zr * 68 + zc]           = acc[mi][f][0];
                            z[zr * 68 + zc + 1]       = acc[mi][f][1];
                            z[(zr + 8) * 68 + zc]     = acc[mi][f][2];
                            z[(zr + 8) * 68 + zc + 1] = acc[mi][f][3];
                        } else {
                            z[zr * 68 + zc]           += acc[mi][f][0];
                            z[zr * 68 + zc + 1]       += acc[mi][f][1];
                            z[(zr + 8) * 68 + zc]     += acc[mi][f][2];
                            z[(zr + 8) * 68 + zc + 1] += acc[mi][f][3];
                        }
                    }
            }
            __syncthreads();
        }

        // ---- LSTM cell epilogue (c kept in registers) ----
        const float* bias = g_bias[sel] + j0;
        const int wp = p ^ 1;
#pragma unroll
        for (int it = 0; it < 2; ++it) {
            int e = tid + it * 512;
            int bl_ = e >> 4, cl = e & 15;
            float zi = z[bl_ * 68 + cl * 4 + 0] + bias[cl * 4 + 0];
            float zf = z[bl_ * 68 + cl * 4 + 1] + bias[cl * 4 + 1];
            float zg = z[bl_ * 68 + cl * 4 + 2] + bias[cl * 4 + 2];
            float zo = z[bl_ * 68 + cl * 4 + 3] + bias[cl * 4 + 3];
            float ig = sigmoidf_(zi);
            float fg = sigmoidf_(zf);
            float gg = tanhf_(zg);
            float og = sigmoidf_(zo);
            float cN = fg * creg[it] + ig * gg;
            float hN = og * tanhf_(cN);
            creg[it] = cN;
            int ci = (b0 + bl_) * HH + c0 + cl;
            __nv_bfloat16 hh = __float2bfloat16(hN);
            g_h_hi[wp][ci] = hh;
            g_h_lo[wp][ci] = __float2bfloat16(hN - __bfloat162float(hh));
            if (t >= TENC)
                hid_base[(size_t)(b0 + bl_) * (TDEC * HH) + (t - TENC) * HH + c0 + cl] = hN;
        }

        // ---- grid-wide barrier (skip after last step) ----
        if (t + 1 < TT) {
            mygen++;
            __syncthreads();
            __threadfence();
            if (tid == 0) {
                unsigned prev = atomicAdd(&g_bar_arrive, 1u);
                if (prev == (unsigned)NCTA * mygen - 1u) {
                    atomicExch(&g_bar_gen, mygen);
                } else {
                    while (atomicAdd(&g_bar_gen, 0u) < mygen) {}
                }
            }
            __syncthreads();
        }
    }
}

// ---------------- final output projection ----------------
struct STiles {
    __nv_bfloat16 Ah[2][32][36];
    __nv_bfloat16 Al[2][32][36];
    __nv_bfloat16 Bh[2][128][36];
    __nv_bfloat16 Bl[2][128][36];
};
union SU {
    STiles t;
    float z[32][132];
};

__global__ __launch_bounds__(256) void proj_kernel(const float* __restrict__ hid,
                                                   const float* __restrict__ outb,
                                                   float* __restrict__ out) {
    __shared__ SU su;
    const int tid = threadIdx.x;
    const int lane = tid & 31;
    const int warp = tid >> 5;
    const int wm = (warp & 1) * 16;
    const int wn = (warp >> 1) * 32;
    const int m0 = blockIdx.y * 32;
    const int n0 = blockIdx.x * 128;

    float acc[4][4];
#pragma unroll
    for (int s = 0; s < 4; ++s)
#pragma unroll
        for (int i = 0; i < 4; ++i) acc[s][i] = 0.f;

#pragma unroll
    for (int j = 0; j < 4; ++j) {
        int i = tid + j * 256;
        int row = i >> 5, k = i & 31;
        float v = hid[(m0 + row) * HH + k];
        __nv_bfloat16 hi = __float2bfloat16(v);
        su.t.Ah[0][row][k] = hi;
        su.t.Al[0][row][k] = __float2bfloat16(v - __bfloat162float(hi));
    }
#pragma unroll
    for (int j = 0; j < 8; ++j) {
        int i = tid + j * 256;
        int row = i >> 4, k2 = (i & 15) * 2;
        int off = (n0 + row) * HH + k2;
        *(uint32_t*)&su.t.Bh[0][row][k2] = *(const uint32_t*)(g_Wo_hi + off);
        *(uint32_t*)&su.t.Bl[0][row][k2] = *(const uint32_t*)(g_Wo_lo + off);
    }

    float pv[4];
    uint32_t pBh[8], pBl[8];
    const int NCHP = HH / 32;

    for (int kc = 0; kc < NCHP; ++kc) {
        __syncthreads();
        const int q = kc & 1;
        if (kc + 1 < NCHP) {
            const int kn = kc + 1;
#pragma unroll
            for (int j = 0; j < 4; ++j) {
                int i = tid + j * 256;
                int row = i >> 5, k = i & 31;
                pv[j] = hid[(m0 + row) * HH + kn * 32 + k];
            }
#pragma unroll
            for (int j = 0; j < 8; ++j) {
                int i = tid + j * 256;
                int row = i >> 4, k2 = (i & 15) * 2;
                int off = (n0 + row) * HH + kn * 32 + k2;
                pBh[j] = *(const uint32_t*)(g_Wo_hi + off);
                pBl[j] = *(const uint32_t*)(g_Wo_lo + off);
            }
        }
#pragma unroll
        for (int k16 = 0; k16 < 2; ++k16) {
            const int ar = wm + (lane >> 2);
            const int ac = (lane & 3) * 2 + k16 * 16;
            uint32_t ah0 = *(const uint32_t*)&su.t.Ah[q][ar][ac];
            uint32_t ah1 = *(const uint32_t*)&su.t.Ah[q][ar + 8][ac];
            uint32_t ah2 = *(const uint32_t*)&su.t.Ah[q][ar][ac + 8];
            uint32_t ah3 = *(const uint32_t*)&su.t.Ah[q][ar + 8][ac + 8];
            uint32_t al0 = *(const uint32_t*)&su.t.Al[q][ar][ac];
            uint32_t al1 = *(const uint32_t*)&su.t.Al[q][ar + 8][ac];
            uint32_t al2 = *(const uint32_t*)&su.t.Al[q][ar][ac + 8];
            uint32_t al3 = *(const uint32_t*)&su.t.Al[q][ar + 8][ac + 8];
#pragma unroll
            for (int s = 0; s < 4; ++s) {
                const int br = wn + s * 8 + (lane >> 2);
                const int bc = (lane & 3) * 2 + k16 * 16;
                uint32_t bh0 = *(const uint32_t*)&su.t.Bh[q][br][bc];
                uint32_t bh1 = *(const uint32_t*)&su.t.Bh[q][br][bc + 8];
                uint32_t bl0 = *(const uint32_t*)&su.t.Bl[q][br][bc];
                uint32_t bl1 = *(const uint32_t*)&su.t.Bl[q][br][bc + 8];
                mma_bf16(acc[s], ah0, ah1, ah2, ah3, bh0, bh1);
                mma_bf16(acc[s], ah0, ah1, ah2, ah3, bl0, bl1);
                mma_bf16(acc[s], al0, al1, al2, al3, bh0, bh1);
            }
        }
        if (kc + 1 < NCHP) {
            const int qn = q ^ 1;
#pragma unroll
            for (int j = 0; j < 4; ++j) {
                int i = tid + j * 256;
                int row = i >> 5, k = i & 31;
                __nv_bfloat16 hi = __float2bfloat16(pv[j]);
                su.t.Ah[qn][row][k] = hi;
                su.t.Al[qn][row][k] = __float2bfloat16(pv[j] - __bfloat162float(hi));
            }
#pragma unroll
            for (int j = 0; j < 8; ++j) {
                int i = tid + j * 256;
                int row = i >> 4, k2 = (i & 15) * 2;
                *(uint32_t*)&su.t.Bh[qn][row][k2] = pBh[j];
                *(uint32_t*)&su.t.Bl[qn][row][k2] = pBl[j];
            }
        }
    }

#pragma unroll
    for (int s = 0; s < 4; ++s) {
        const int r = m0 + wm + (lane >> 2);
        const int cc = n0 + wn + s * 8 + (lane & 3) * 2;
        out[(size_t)r * OO + cc]           = acc[s][0] + outb[cc];
        out[(size_t)r * OO + cc + 1]       = acc[s][1] + outb[cc + 1];
        out[(size_t)(r + 8) * OO + cc]     = acc[s][2] + outb[cc];
        out[(size_t)(r + 8) * OO + cc + 1] = acc[s][3] + outb[cc + 1];
    }
}

// ---------------- launch ----------------
extern "C" void kernel_launch(void* const* d_in, const int* in_sizes, int n_in,
                              void* d_out, int out_size) {
    const float* enc_inp = (const float*)d_in[0];
    const float* dec_inp = (const float*)d_in[1];
    const float* eWih = (const float*)d_in[2];
    const float* eWhh = (const float*)d_in[3];
    const float* ebih = (const float*)d_in[4];
    const float* ebhh = (const float*)d_in[5];
    const float* dWih = (const float*)d_in[6];
    const float* dWhh = (const float*)d_in[7];
    const float* dbih = (const float*)d_in[8];
    const float* dbhh = (const float*)d_in[9];
    const float* outW = (const float*)d_in[10];
    const float* outb = (const float*)d_in[11];
    float* out = (float*)d_out;

    static int configured = 0;
    if (!configured) {
        cudaFuncSetAttribute(lstm_persist, cudaFuncAttributeMaxDynamicSharedMemorySize,
                             SMEM_DYN);
        configured = 1;
    }

    prep_weights<<<256, 256>>>(eWih, eWhh, ebih, ebhh, dWih, dWhh, dbih, dbhh, outW);
    prep_x<<<2048, 256>>>(enc_inp, dec_inp);
    init_state<<<512, 256>>>();

    float* hid_base = out + OUT_OFS;
    lstm_persist<<<dim3(32, 4), 512, SMEM_DYN>>>(hid_base);
    proj_kernel<<<dim3(4, 512), 256>>>(hid_base, outb, out);
}

// round 5
// speedup vs baseline: 2.3200x; 1.2739x over previous
#include <cuda_runtime.h>
#include <cuda_bf16.h>
#include <cuda_fp16.h>
#include <cstdint>

#define BB 256
#define TENC 512
#define TDEC 64
#define TT (TENC + TDEC)
#define DD 64
#define HH 512
#define OO 512
#define G4 2048            // 4*H
#define KHX 576            // H + D
#define OUT_OFS ((size_t)BB * TDEC * OO)

// smem layout (dynamic), bytes:
//  W_hi @ 0       : 64 rows x 1168 B  = 74752
//  W_lo @ 74752   : same              -> 149504
//  A stages @ 149504: 3 x 9216 (Ah[64][144B], fp16 single)
//  zA aliases @149504 (64x68 f32 = 17408); zB @ +17408
#define WLO_OFS 74752u
#define ABASE   149504u
#define ASTG    9216u
#define SMEM_DYN 184320

// ---------------- device-global scratch ----------------
__device__ __align__(16) __half g_W_hi[2][G4 * KHX];
__device__ __align__(16) __half g_W_lo[2][G4 * KHX];
__device__ __align__(16) float  g_bias[2][G4];
__device__ __align__(16) __half g_x[TT * BB * DD];
__device__ __align__(16) __half g_h[2][BB * HH];
__device__ __align__(16) __nv_bfloat16 g_Wo_hi[OO * HH];
__device__ __align__(16) __nv_bfloat16 g_Wo_lo[OO * HH];
__device__ unsigned g_arrive[4];
__device__ unsigned g_gen[4];

// ---------------- helpers ----------------
__device__ __forceinline__ void mma_f16(float (&c)[4],
                                        uint32_t a0, uint32_t a1, uint32_t a2, uint32_t a3,
                                        uint32_t b0, uint32_t b1) {
    asm volatile(
        "mma.sync.aligned.m16n8k16.row.col.f32.f16.f16.f32 "
        "{%0,%1,%2,%3}, {%4,%5,%6,%7}, {%8,%9}, {%0,%1,%2,%3};\n"
        : "+f"(c[0]), "+f"(c[1]), "+f"(c[2]), "+f"(c[3])
        : "r"(a0), "r"(a1), "r"(a2), "r"(a3), "r"(b0), "r"(b1));
}

__device__ __forceinline__ void mma_bf16(float (&c)[4],
                                         uint32_t a0, uint32_t a1, uint32_t a2, uint32_t a3,
                                         uint32_t b0, uint32_t b1) {
    asm volatile(
        "mma.sync.aligned.m16n8k16.row.col.f32.bf16.bf16.f32 "
        "{%0,%1,%2,%3}, {%4,%5,%6,%7}, {%8,%9}, {%0,%1,%2,%3};\n"
        : "+f"(c[0]), "+f"(c[1]), "+f"(c[2]), "+f"(c[3])
        : "r"(a0), "r"(a1), "r"(a2), "r"(a3), "r"(b0), "r"(b1));
}

__device__ __forceinline__ void ldsm4(uint32_t* r, uint32_t addr) {
    asm volatile("ldmatrix.sync.aligned.m8n8.x4.shared.b16 {%0,%1,%2,%3}, [%4];\n"
                 : "=r"(r[0]), "=r"(r[1]), "=r"(r[2]), "=r"(r[3]) : "r"(addr));
}

__device__ __forceinline__ void cp16(uint32_t dst, const void* src) {
    asm volatile("cp.async.cg.shared.global [%0], [%1], 16;\n" :: "r"(dst), "l"(src));
}
__device__ __forceinline__ void cp_commit() { asm volatile("cp.async.commit_group;\n"); }
template <int N> __device__ __forceinline__ void cp_wait() {
    asm volatile("cp.async.wait_group %0;\n" :: "n"(N));
}

__device__ __forceinline__ float sigmoidf_(float x) { return 1.f / (1.f + __expf(-x)); }
__device__ __forceinline__ float tanhf_(float x) { return 1.f - 2.f / (__expf(2.f * x) + 1.f); }

// ---------------- prep kernels ----------------
__global__ void prep_weights(const float* __restrict__ eWih, const float* __restrict__ eWhh,
                             const float* __restrict__ ebih, const float* __restrict__ ebhh,
                             const float* __restrict__ dWih, const float* __restrict__ dWhh,
                             const float* __restrict__ dbih, const float* __restrict__ dbhh,
                             const float* __restrict__ outW) {
    int idx = blockIdx.x * blockDim.x + threadIdx.x;
    int stride = gridDim.x * blockDim.x;
    for (int i = idx; i < 2 * G4 * KHX; i += stride) {
        int sel = i / (G4 * KHX);
        int r = i - sel * (G4 * KHX);
        int jr = r / KHX;
        int k = r - jr * KHX;
        int gate = jr & 3, col = jr >> 2;
        int js = gate * HH + col;
        const float* Wih = sel ? dWih : eWih;
        const float* Whh = sel ? dWhh : eWhh;
        float w = (k < HH) ? Whh[js * HH + k] : Wih[js * DD + (k - HH)];
        __half hi = __float2half(w);
        g_W_hi[sel][jr * KHX + k] = hi;
        g_W_lo[sel][jr * KHX + k] = __float2half(w - __half2float(hi));
    }
    for (int i = idx; i < 2 * G4; i += stride) {
        int sel = i >> 11;
        int jr = i & (G4 - 1);
        int gate = jr & 3, col = jr >> 2;
        int js = gate * HH + col;
        g_bias[sel][jr] = sel ? (dbih[js] + dbhh[js]) : (ebih[js] + ebhh[js]);
    }
    for (int i = idx; i < OO * HH; i += stride) {
        float w = outW[i];
        __nv_bfloat16 hi = __float2bfloat16(w);
        g_Wo_hi[i] = hi;
        g_Wo_lo[i] = __float2bfloat16(w - __bfloat162float(hi));
    }
}

__global__ void prep_x(const float* __restrict__ enc, const float* __restrict__ dec) {
    int idx = blockIdx.x * blockDim.x + threadIdx.x;
    int stride = gridDim.x * blockDim.x;
    const int total = TT * BB * DD;
    for (int i = idx; i < total; i += stride) {
        int t = i / (BB * DD);
        int r = i - t * (BB * DD);
        int b = r / DD;
        int d = r - b * DD;
        float v = (t < TENC) ? enc[(b * TENC + t) * DD + d]
                             : dec[(b * TDEC + (t - TENC)) * DD + d];
        g_x[i] = __float2half(v);
    }
}

__global__ void init_state() {
    int idx = blockIdx.x * blockDim.x + threadIdx.x;
    int stride = gridDim.x * blockDim.x;
    if (idx < 4) { g_arrive[idx] = 0; g_gen[idx] = 0; }
    for (int i = idx; i < BB * HH; i += stride) {
        g_h[0][i] = __float2half(0.f);
        g_h[1][i] = __float2half(0.f);
    }
}

// ---------------- persistent LSTM kernel ----------------
// grid (32 n-blocks, 4 m-blocks) = 128 CTAs; 512 threads = 16 warps: nw2 x mw2 x kw4
// CTA tile per step: M=64 batch x N=64 gate-rows x K=576 (9 chunks of k64)
// chunk 8 = x (h-independent, prefetched across the barrier)
__global__ __launch_bounds__(512, 1) void lstm_persist(float* __restrict__ hid_base) {
    extern __shared__ __align__(16) char sm[];
    const uint32_t sbase = (uint32_t)__cvta_generic_to_shared(sm);
    const int tid = threadIdx.x;
    const int lane = tid & 31;
    const int warp = tid >> 5;
    const int nw = warp & 1;
    const int mw = (warp >> 1) & 1;
    const int kw = warp >> 2;
    const int j0 = blockIdx.x * 64;   // gate-row base
    const int b0 = blockIdx.y * 64;   // batch base
    const int gm = blockIdx.y;        // barrier group
    const int c0 = j0 >> 2;           // h-column base

    auto loadW = [&](int sel) {
        for (int i = tid; i < 9216; i += 512) {
            int s2 = (i >= 4608);
            int rem = s2 ? i - 4608 : i;
            int r = rem / 72, u = rem - r * 72;
            uint32_t dst = sbase + (s2 ? WLO_OFS : 0u) + r * 1168 + u * 16;
            const __half* src = (s2 ? g_W_lo[sel] : g_W_hi[sel]) + (j0 + r) * KHX + u * 8;
            cp16(dst, src);
        }
        cp_commit();
        cp_wait<0>();
        __syncthreads();
    };
    loadW(0);

    // cell state resident in registers
    float creg[2] = {0.f, 0.f};
    unsigned mygen = 0;

    const int fr = lane & 15;
    const int fhalf = (lane >> 4) * 16;

    // A-chunk issue: c = 0..7 from h (parity p), c = 8 from x (step offset xofs)
    auto issueA = [&](int c, int stg, int p, int xofs) {
        uint32_t st = sbase + ABASE + (uint32_t)(stg * ASTG);
        int r = tid >> 3, u = tid & 7;
        uint32_t dst = st + r * 144 + u * 16;
        const __half* src = (c < 8)
            ? g_h[p] + (b0 + r) * HH + c * 64 + u * 8
            : g_x + xofs + (b0 + r) * DD + u * 8;
        cp16(dst, src);
    };

    float acc[2][4][4];

    // prefetch x chunk for t=0
    issueA(8, 0, 0, 0);
    cp_commit();

    for (int t = 0; t < TT; ++t) {
        const int p = t & 1;
        const int sel = (t >= TENC);
        const int xofs = t * BB * DD;

        // ---- barrier: wait for h of step t-1 (group gm only) ----
        if (t > 0) {
            if (tid == 0) {
                unsigned g;
                do {
                    asm volatile("ld.acquire.gpu.global.u32 %0, [%1];"
                                 : "=r"(g) : "l"(&g_gen[gm]));
                } while (g < mygen);
            }
            __syncthreads();
        }
        if (t == TENC) loadW(1);

#pragma unroll
        for (int mi = 0; mi < 2; ++mi)
#pragma unroll
            for (int f = 0; f < 4; ++f)
#pragma unroll
                for (int e = 0; e < 4; ++e) acc[mi][f][e] = 0.f;

        auto compute = [&](int stg, int c) {
            uint32_t st = sbase + ABASE + (uint32_t)(stg * ASTG);
            uint32_t ah[8], bh[8], bl[8];
            uint32_t aaddr = st + (mw * 32 + fr) * 144 + kw * 32 + fhalf;
            ldsm4(ah, aaddr);
            ldsm4(ah + 4, aaddr + 16 * 144);
            uint32_t kb = (uint32_t)(c * 128 + kw * 32) + fhalf;
#pragma unroll
            for (int g = 0; g < 2; ++g) {
                uint32_t baddr = sbase + (nw * 32 + g * 16 + fr) * 1168 + kb;
                ldsm4(&bh[g * 4], baddr);
                ldsm4(&bl[g * 4], baddr + WLO_OFS);
            }
#pragma unroll
            for (int mi = 0; mi < 2; ++mi)
#pragma unroll
                for (int f = 0; f < 4; ++f) {
                    uint32_t b0h = bh[(f >> 1) * 4 + (f & 1)];
                    uint32_t b1h = bh[(f >> 1) * 4 + 2 + (f & 1)];
                    uint32_t b0l = bl[(f >> 1) * 4 + (f & 1)];
                    uint32_t b1l = bl[(f >> 1) * 4 + 2 + (f & 1)];
                    mma_f16(acc[mi][f], ah[mi * 4], ah[mi * 4 + 1], ah[mi * 4 + 2],
                            ah[mi * 4 + 3], b0h, b1h);
                    mma_f16(acc[mi][f], ah[mi * 4], ah[mi * 4 + 1], ah[mi * 4 + 2],
                            ah[mi * 4 + 3], b0l, b1l);
                }
        };

        // chunk processing order: [8 (x, prefetched), 0..7 (h)]
        issueA(0, 1, p, xofs); cp_commit();
        for (int i = 0; i < 9; ++i) {
            if (i == 8) cp_wait<0>(); else cp_wait<1>();
            __syncthreads();
            if (i + 2 < 9) { issueA(i + 1, (i + 2) % 3, p, xofs); cp_commit(); }
            compute(i % 3, (i == 0) ? 8 : (i - 1));
        }
        __syncthreads();

        // ---- kw reduction: 2 rounds into zA/zB (alias A stages) ----
        float* zA = (float*)(sm + ABASE);
        float* zB = zA + 4352;           // 17408 bytes
        float* zt = (kw & 1) ? zB : zA;
#pragma unroll
        for (int rnd = 0; rnd < 2; ++rnd) {
            if ((kw >> 1) == rnd) {
#pragma unroll
                for (int mi = 0; mi < 2; ++mi)
#pragma unroll
                    for (int f = 0; f < 4; ++f) {
                        int zr = mw * 32 + mi * 16 + (lane >> 2);
                        int zc = nw * 32 + f * 8 + (lane & 3) * 2;
                        if (rnd == 0) {
                            zt[zr * 68 + zc]           = acc[mi][f][0];
                            zt[zr * 68 + zc + 1]       = acc[mi][f][1];
                            zt[(zr + 8) * 68 + zc]     = acc[mi][f][2];
                            zt[(zr + 8) * 68 + zc + 1] = acc[mi][f][3];
                        } else {
                            zt[zr * 68 + zc]           += acc[mi][f][0];
                            zt[zr * 68 + zc + 1]       += acc[mi][f][1];
                            zt[(zr + 8) * 68 + zc]     += acc[mi][f][2];
                            zt[(zr + 8) * 68 + zc + 1] += acc[mi][f][3];
                        }
                    }
            }
            __syncthreads();
        }

        // ---- LSTM cell epilogue (c in registers) ----
        const float* bias = g_bias[sel] + j0;
        const int wp = p ^ 1;
#pragma unroll
        for (int it = 0; it < 2; ++it) {
            int e = tid + it * 512;
            int bl_ = e >> 4, cl = e & 15;
            float zi = zA[bl_ * 68 + cl * 4 + 0] + zB[bl_ * 68 + cl * 4 + 0] + bias[cl * 4 + 0];
            float zf = zA[bl_ * 68 + cl * 4 + 1] + zB[bl_ * 68 + cl * 4 + 1] + bias[cl * 4 + 1];
            float zg = zA[bl_ * 68 + cl * 4 + 2] + zB[bl_ * 68 + cl * 4 + 2] + bias[cl * 4 + 2];
            float zo = zA[bl_ * 68 + cl * 4 + 3] + zB[bl_ * 68 + cl * 4 + 3] + bias[cl * 4 + 3];
            float ig = sigmoidf_(zi);
            float fg = sigmoidf_(zf);
            float gg = tanhf_(zg);
            float og = sigmoidf_(zo);
            float cN = fg * creg[it] + ig * gg;
            float hN = og * tanhf_(cN);
            creg[it] = cN;
            int ci = (b0 + bl_) * HH + c0 + cl;
            g_h[wp][ci] = __float2half(hN);
            if (t >= TENC)
                hid_base[(size_t)(b0 + bl_) * (TDEC * HH) + (t - TENC) * HH + c0 + cl] = hN;
        }

        __syncthreads();  // z reads done; stage0 safe to overwrite

        if (t + 1 < TT) {
            // prefetch x chunk of next step (h-independent) — overlaps barrier
            issueA(8, 0, 0, (t + 1) * BB * DD);
            cp_commit();
            // arrive: h of step t is published
            mygen++;
            __threadfence();
            if (tid == 0) {
                unsigned prev = atomicAdd(&g_arrive[gm], 1u);
                if (prev == 32u * mygen - 1u) {
                    asm volatile("st.release.gpu.global.u32 [%0], %1;"
                                 :: "l"(&g_gen[gm]), "r"(mygen));
                }
            }
        }
    }
}

// ---------------- final output projection (bf16 3-term, unchanged) ----------------
struct STiles {
    __nv_bfloat16 Ah[2][32][36];
    __nv_bfloat16 Al[2][32][36];
    __nv_bfloat16 Bh[2][128][36];
    __nv_bfloat16 Bl[2][128][36];
};
union SU {
    STiles t;
    float z[32][132];
};

__global__ __launch_bounds__(256) void proj_kernel(const float* __restrict__ hid,
                                                   const float* __restrict__ outb,
                                                   float* __restrict__ out) {
    __shared__ SU su;
    const int tid = threadIdx.x;
    const int lane = tid & 31;
    const int warp = tid >> 5;
    const int wm = (warp & 1) * 16;
    const int wn = (warp >> 1) * 32;
    const int m0 = blockIdx.y * 32;
    const int n0 = blockIdx.x * 128;

    float acc[4][4];
#pragma unroll
    for (int s = 0; s < 4; ++s)
#pragma unroll
        for (int i = 0; i < 4; ++i) acc[s][i] = 0.f;

#pragma unroll
    for (int j = 0; j < 4; ++j) {
        int i = tid + j * 256;
        int row = i >> 5, k = i & 31;
        float v = hid[(m0 + row) * HH + k];
        __nv_bfloat16 hi = __float2bfloat16(v);
        su.t.Ah[0][row][k] = hi;
        su.t.Al[0][row][k] = __float2bfloat16(v - __bfloat162float(hi));
    }
#pragma unroll
    for (int j = 0; j < 8; ++j) {
        int i = tid + j * 256;
        int row = i >> 4, k2 = (i & 15) * 2;
        int off = (n0 + row) * HH + k2;
        *(uint32_t*)&su.t.Bh[0][row][k2] = *(const uint32_t*)(g_Wo_hi + off);
        *(uint32_t*)&su.t.Bl[0][row][k2] = *(const uint32_t*)(g_Wo_lo + off);
    }

    float pv[4];
    uint32_t pBh[8], pBl[8];
    const int NCHP = HH / 32;

    for (int kc = 0; kc < NCHP; ++kc) {
        __syncthreads();
        const int q = kc & 1;
        if (kc + 1 < NCHP) {
            const int kn = kc + 1;
#pragma unroll
            for (int j = 0; j < 4; ++j) {
                int i = tid + j * 256;
                int row = i >> 5, k = i & 31;
                pv[j] = hid[(m0 + row) * HH + kn * 32 + k];
            }
#pragma unroll
            for (int j = 0; j < 8; ++j) {
                int i = tid + j * 256;
                int row = i >> 4, k2 = (i & 15) * 2;
                int off = (n0 + row) * HH + kn * 32 + k2;
                pBh[j] = *(const uint32_t*)(g_Wo_hi + off);
                pBl[j] = *(const uint32_t*)(g_Wo_lo + off);
            }
        }
#pragma unroll
        for (int k16 = 0; k16 < 2; ++k16) {
            const int ar = wm + (lane >> 2);
            const int ac = (lane & 3) * 2 + k16 * 16;
            uint32_t ah0 = *(const uint32_t*)&su.t.Ah[q][ar][ac];
            uint32_t ah1 = *(const uint32_t*)&su.t.Ah[q][ar + 8][ac];
            uint32_t ah2 = *(const uint32_t*)&su.t.Ah[q][ar][ac + 8];
            uint32_t ah3 = *(const uint32_t*)&su.t.Ah[q][ar + 8][ac + 8];
            uint32_t al0 = *(const uint32_t*)&su.t.Al[q][ar][ac];
            uint32_t al1 = *(const uint32_t*)&su.t.Al[q][ar + 8][ac];
            uint32_t al2 = *(const uint32_t*)&su.t.Al[q][ar][ac + 8];
            uint32_t al3 = *(const uint32_t*)&su.t.Al[q][ar + 8][ac + 8];
#pragma unroll
            for (int s = 0; s < 4; ++s) {
                const int br = wn + s * 8 + (lane >> 2);
                const int bc = (lane & 3) * 2 + k16 * 16;
                uint32_t bh0 = *(const uint32_t*)&su.t.Bh[q][br][bc];
                uint32_t bh1 = *(const uint32_t*)&su.t.Bh[q][br][bc + 8];
                uint32_t bl0 = *(const uint32_t*)&su.t.Bl[q][br][bc];
                uint32_t bl1 = *(const uint32_t*)&su.t.Bl[q][br][bc + 8];
                mma_bf16(acc[s], ah0, ah1, ah2, ah3, bh0, bh1);
                mma_bf16(acc[s], ah0, ah1, ah2, ah3, bl0, bl1);
                mma_bf16(acc[s], al0, al1, al2, al3, bh0, bh1);
            }
        }
        if (kc + 1 < NCHP) {
            const int qn = q ^ 1;
#pragma unroll
            for (int j = 0; j < 4; ++j) {
                int i = tid + j * 256;
                int row = i >> 5, k = i & 31;
                __nv_bfloat16 hi = __float2bfloat16(pv[j]);
                su.t.Ah[qn][row][k] = hi;
                su.t.Al[qn][row][k] = __float2bfloat16(pv[j] - __bfloat162float(hi));
            }
#pragma unroll
            for (int j = 0; j < 8; ++j) {
                int i = tid + j * 256;
                int row = i >> 4, k2 = (i & 15) * 2;
                *(uint32_t*)&su.t.Bh[qn][row][k2] = pBh[j];
                *(uint32_t*)&su.t.Bl[qn][row][k2] = pBl[j];
            }
        }
    }

#pragma unroll
    for (int s = 0; s < 4; ++s) {
        const int r = m0 + wm + (lane >> 2);
        const int cc = n0 + wn + s * 8 + (lane & 3) * 2;
        out[(size_t)r * OO + cc]           = acc[s][0] + outb[cc];
        out[(size_t)r * OO + cc + 1]       = acc[s][1] + outb[cc + 1];
        out[(size_t)(r + 8) * OO + cc]     = acc[s][2] + outb[cc];
        out[(size_t)(r + 8) * OO + cc + 1] = acc[s][3] + outb[cc + 1];
    }
}

// ---------------- launch ----------------
extern "C" void kernel_launch(void* const* d_in, const int* in_sizes, int n_in,
                              void* d_out, int out_size) {
    const float* enc_inp = (const float*)d_in[0];
    const float* dec_inp = (const float*)d_in[1];
    const float* eWih = (const float*)d_in[2];
    const float* eWhh = (const float*)d_in[3];
    const float* ebih = (const float*)d_in[4];
    const float* ebhh = (const float*)d_in[5];
    const float* dWih = (const float*)d_in[6];
    const float* dWhh = (const float*)d_in[7];
    const float* dbih = (const float*)d_in[8];
    const float* dbhh = (const float*)d_in[9];
    const float* outW = (const float*)d_in[10];
    const float* outb = (const float*)d_in[11];
    float* out = (float*)d_out;

    static int configured = 0;
    if (!configured) {
        cudaFuncSetAttribute(lstm_persist, cudaFuncAttributeMaxDynamicSharedMemorySize,
                             SMEM_DYN);
        configured = 1;
    }

    prep_weights<<<256, 256>>>(eWih, eWhh, ebih, ebhh, dWih, dWhh, dbih, dbhh, outW);
    prep_x<<<2048, 256>>>(enc_inp, dec_inp);
    init_state<<<512, 256>>>();

    float* hid_base = out + OUT_OFS;
    lstm_persist<<<dim3(32, 4), 512, SMEM_DYN>>>(hid_base);
    proj_kernel<<<dim3(4, 512), 256>>>(hid_base, outb, out);
}